// round 5
// baseline (speedup 1.0000x reference)
#include <cuda_runtime.h>
#include <cuda_bf16.h>
#include <math.h>
#include <stdint.h>

// Problem constants
#define B   8
#define T   16
#define CIN 3
#define HID 64
#define HW  64
#define PIX (HW*HW)          // 4096

#define KC   8               // input-channel chunk held in smem
#define INW  68              // padded input row width (1 left halo + 64 + 1 right halo + 2 pad)

// ---------------- scratch (no allocation allowed) ----------------
__device__ float g_xin[B*T*CIN*PIX];          // attention-scaled input
__device__ float g_h0[2][B*HID*PIX];          // layer0 hidden, double buffered
__device__ float g_c0[B*HID*PIX];             // layer0 cell
__device__ float g_h1[2][B*HID*PIX];          // layer1 hidden, double buffered
__device__ float g_c1[B*HID*PIX];             // layer1 cell

// ---------------- packed f32x2 helpers ----------------
__device__ __forceinline__ uint64_t pack2u(uint32_t lo, uint32_t hi) {
    uint64_t r; asm("mov.b64 %0, {%1,%2};" : "=l"(r) : "r"(lo), "r"(hi)); return r;
}
__device__ __forceinline__ uint64_t midpair(uint64_t a, uint64_t b) {
    // returns { hi(a), lo(b) }
    uint32_t alo, ahi, blo, bhi;
    asm("mov.b64 {%0,%1}, %2;" : "=r"(alo), "=r"(ahi) : "l"(a));
    asm("mov.b64 {%0,%1}, %2;" : "=r"(blo), "=r"(bhi) : "l"(b));
    return pack2u(ahi, blo);
}
__device__ __forceinline__ void fma2(uint64_t& d, uint64_t a, uint64_t w) {
    asm("fma.rn.f32x2 %0, %1, %2, %0;" : "+l"(d) : "l"(a), "l"(w));
}
__device__ __forceinline__ void unpack2(uint64_t v, float& lo, float& hi) {
    uint32_t l, h;
    asm("mov.b64 {%0,%1}, %2;" : "=r"(l), "=r"(h) : "l"(v));
    lo = __uint_as_float(l); hi = __uint_as_float(h);
}

// ---------------- attention + input scaling ----------------
__global__ void attention_kernel(const float* __restrict__ x,
                                 const float* __restrict__ w1,
                                 const float* __restrict__ w2,
                                 float* __restrict__ xin)
{
    const int bt = blockIdx.x;                 // 0..127
    const float* xp = x  + (long)bt * CIN * PIX;
    float*       xo = xin + (long)bt * CIN * PIX;

    __shared__ float s_sum[256], s_max[256];
    __shared__ float chAvg[CIN], chMax[CIN], scale[CIN];

    for (int c = 0; c < CIN; ++c) {
        float s = 0.f, m = -INFINITY;
        for (int i = threadIdx.x; i < PIX; i += 256) {
            float v = xp[c*PIX + i];
            s += v; m = fmaxf(m, v);
        }
        s_sum[threadIdx.x] = s; s_max[threadIdx.x] = m;
        __syncthreads();
        for (int off = 128; off > 0; off >>= 1) {
            if (threadIdx.x < off) {
                s_sum[threadIdx.x] += s_sum[threadIdx.x + off];
                s_max[threadIdx.x] = fmaxf(s_max[threadIdx.x], s_max[threadIdx.x + off]);
            }
            __syncthreads();
        }
        if (threadIdx.x == 0) { chAvg[c] = s_sum[0] / (float)PIX; chMax[c] = s_max[0]; }
        __syncthreads();
    }
    if (threadIdx.x == 0) {
        float ha = w1[0]*chAvg[0] + w1[1]*chAvg[1] + w1[2]*chAvg[2];
        float hm = w1[0]*chMax[0] + w1[1]*chMax[1] + w1[2]*chMax[2];
        ha = fmaxf(ha, 0.f); hm = fmaxf(hm, 0.f);
        float hs = ha + hm;
        for (int c = 0; c < CIN; ++c)
            scale[c] = 1.f / (1.f + expf(-w2[c]*hs));
    }
    __syncthreads();
    for (int c = 0; c < CIN; ++c)
        for (int i = threadIdx.x; i < PIX; i += 256)
            xo[c*PIX + i] = xp[c*PIX + i] * scale[c];
}

// ---------------- fused conv(3x3 SAME) + LSTM pointwise step ----------------
// grid: (16 row-tiles, 8 hidden-groups, 8 batches), 256 threads.
// Warp owns one hidden channel; lane owns adjacent column pair (2*lane, 2*lane+1)
// for 4 rows -> 4 gates x 4 rows of f32x2 accumulators (packed pairs).
__global__ __launch_bounds__(256)
void convlstm_step(const float* __restrict__ srcA, int CA, long sA,
                   const float* __restrict__ srcB, long sB,
                   int Cin,
                   const float* __restrict__ W,        // [4*HID, Cin, 3,3]
                   const float* __restrict__ bias,     // [4*HID]
                   float* __restrict__ cState,         // [B,HID,PIX] in/out
                   float* __restrict__ hOut,  long hOutStride,
                   float* __restrict__ hOut2, long hOut2Stride,
                   float* __restrict__ hFin,  float* __restrict__ cFin)
{
    const int b    = blockIdx.z;
    const int warp = threadIdx.x >> 5;
    const int lane = threadIdx.x & 31;
    const int j    = blockIdx.y * 8 + warp;    // hidden channel
    const int r0   = blockIdx.x * 4;           // first output row

    __shared__ __align__(16) float in_s[KC*6*INW];      // [kc][6 rows][68 cols]
    __shared__ __align__(16) float w_s[8*KC*9*8];       // [wj][kc][kk][gate*2 dup]

    uint64_t acc[4][4];                                 // [gate][row] packed pairs
    #pragma unroll
    for (int g = 0; g < 4; ++g)
        #pragma unroll
        for (int r = 0; r < 4; ++r) acc[g][r] = 0ull;

    const float* srcAb = srcA + (long)b * sA;
    const float* srcBb = srcB + (long)b * sB;

    for (int c0 = 0; c0 < Cin; c0 += KC) {
        const int kcCnt = min(KC, Cin - c0);
        __syncthreads();
        // ---- stage input tile (array col = global col + 1; zero pad) ----
        const int total = kcCnt * 6 * INW;
        for (int idx = threadIdx.x; idx < total; idx += 256) {
            int col = idx % INW;
            int row = (idx / INW) % 6;
            int kc  = idx / (INW*6);
            int c   = c0 + kc;
            int gr  = r0 + row - 1;
            int gc  = col - 1;
            float v = 0.f;
            if (gr >= 0 && gr < HW && gc >= 0 && gc < HW) {
                v = (c < CA) ? srcAb[(long)c      *PIX + gr*HW + gc]
                             : srcBb[(long)(c-CA) *PIX + gr*HW + gc];
            }
            in_s[idx] = v;
        }
        // ---- stage weights, each duplicated into a {w,w} pair ----
        const int wtotal = 8 * kcCnt * 9 * 8;   // wj * kc * kk * (4 gates x 2 dup)
        for (int idx = threadIdx.x; idx < wtotal; idx += 256) {
            int g   = (idx >> 1) & 3;
            int kk  = (idx >> 3) % 9;
            int kc  = (idx / 72) % kcCnt;
            int wj  = idx / (72 * kcCnt);
            int oc  = g*HID + blockIdx.y*8 + wj;
            float v = W[((long)oc*Cin + c0 + kc)*9 + kk];
            w_s[((wj*KC + kc)*9 + kk)*8 + (idx & 7)] = v;
        }
        __syncthreads();

        // ---- accumulate ----
        for (int kc = 0; kc < kcCnt; ++kc) {
            const float* rp = in_s + kc*6*INW + 2*lane;
            const float* wp = w_s + (warp*KC + kc)*72;
            #pragma unroll
            for (int ky = 0; ky < 3; ++ky) {
                // rows ky..ky+3: load packed pairs for kx = 0,1,2
                uint64_t Lr[4], Mr[4], Rr[4];
                #pragma unroll
                for (int r = 0; r < 4; ++r) {
                    uint64_t u01 = *(const uint64_t*)(rp + (r + ky)*INW);
                    uint64_t u23 = *(const uint64_t*)(rp + (r + ky)*INW + 2);
                    Lr[r] = u01;
                    Mr[r] = midpair(u01, u23);
                    Rr[r] = u23;
                }
                #pragma unroll
                for (int kx = 0; kx < 3; ++kx) {
                    const int kk = ky*3 + kx;
                    ulonglong2 wAB = *(const ulonglong2*)(wp + kk*8);      // {w0,w0},{w1,w1}
                    ulonglong2 wCD = *(const ulonglong2*)(wp + kk*8 + 4);  // {w2,w2},{w3,w3}
                    #pragma unroll
                    for (int r = 0; r < 4; ++r) {
                        uint64_t a = (kx == 0) ? Lr[r] : (kx == 1) ? Mr[r] : Rr[r];
                        fma2(acc[0][r], a, wAB.x);
                        fma2(acc[1][r], a, wAB.y);
                        fma2(acc[2][r], a, wCD.x);
                        fma2(acc[3][r], a, wCD.y);
                    }
                }
            }
        }
    }

    // ---- fused LSTM pointwise update (column pair per lane) ----
    const float bi = bias[j], bf = bias[HID + j], bo = bias[2*HID + j], bg = bias[3*HID + j];
    const long cBase = ((long)b*HID + j)*PIX;
    #pragma unroll
    for (int r = 0; r < 4; ++r) {
        const int  pix  = (r0 + r)*HW + 2*lane;
        const long cOff = cBase + pix;
        float i0,i1, f0,f1, o0,o1, g0,g1;
        unpack2(acc[0][r], i0, i1);
        unpack2(acc[1][r], f0, f1);
        unpack2(acc[2][r], o0, o1);
        unpack2(acc[3][r], g0, g1);

        float2 cOld = *(const float2*)(cState + cOff);

        float ig0 = 1.f/(1.f + __expf(-(i0 + bi)));
        float ig1 = 1.f/(1.f + __expf(-(i1 + bi)));
        float fg0 = 1.f/(1.f + __expf(-(f0 + bf)));
        float fg1 = 1.f/(1.f + __expf(-(f1 + bf)));
        float og0 = 1.f/(1.f + __expf(-(o0 + bo)));
        float og1 = 1.f/(1.f + __expf(-(o1 + bo)));
        float gg0 = tanhf(g0 + bg);
        float gg1 = tanhf(g1 + bg);

        float cN0 = fg0*cOld.x + ig0*gg0;
        float cN1 = fg1*cOld.y + ig1*gg1;
        float hN0 = og0*tanhf(cN0);
        float hN1 = og1*tanhf(cN1);

        *(float2*)(cState + cOff) = make_float2(cN0, cN1);
        *(float2*)(hOut + (long)b*hOutStride + (long)j*PIX + pix) = make_float2(hN0, hN1);
        if (hOut2) *(float2*)(hOut2 + (long)b*hOut2Stride + (long)j*PIX + pix) = make_float2(hN0, hN1);
        if (hFin)  *(float2*)(hFin + cBase + pix) = make_float2(hN0, hN1);
        if (cFin)  *(float2*)(cFin + cBase + pix) = make_float2(cN0, cN1);
    }
}

// ---------------- host ----------------
extern "C" void kernel_launch(void* const* d_in, const int* in_sizes, int n_in,
                              void* d_out, int out_size)
{
    const float* x       = (const float*)d_in[0];
    const float* att_w1  = (const float*)d_in[1];
    const float* att_w2  = (const float*)d_in[2];
    const float* conv_w0 = (const float*)d_in[3];
    const float* conv_b0 = (const float*)d_in[4];
    const float* conv_w1 = (const float*)d_in[5];
    const float* conv_b1 = (const float*)d_in[6];
    float* out = (float*)d_out;

    float *xin, *h0_0, *h0_1, *c0, *h1_0, *h1_1, *c1;
    cudaGetSymbolAddress((void**)&xin,  g_xin);
    cudaGetSymbolAddress((void**)&h0_0, g_h0);   h0_1 = h0_0 + (long)B*HID*PIX;
    cudaGetSymbolAddress((void**)&c0,   g_c0);
    cudaGetSymbolAddress((void**)&h1_0, g_h1);   h1_1 = h1_0 + (long)B*HID*PIX;
    cudaGetSymbolAddress((void**)&c1,   g_c1);

    const size_t stBytes = (size_t)B*HID*PIX*sizeof(float);
    cudaMemsetAsync(h0_0, 0, stBytes);
    cudaMemsetAsync(c0,   0, stBytes);
    cudaMemsetAsync(h1_0, 0, stBytes);
    cudaMemsetAsync(c1,   0, stBytes);

    attention_kernel<<<B*T, 256>>>(x, att_w1, att_w2, xin);

    float* h0buf[2] = {h0_0, h0_1};
    float* h1buf[2] = {h1_0, h1_1};

    float* out1  = out;                                  // [B,T,HID,PIX]
    float* h1fin = out + (long)B*T*HID*PIX;              // [B,HID,PIX]
    float* c1fin = h1fin + (long)B*HID*PIX;              // [B,HID,PIX]

    dim3 grid(HW/4, HID/8, B);

    for (int t = 0; t < T; ++t) {
        const int p = t & 1;
        // layer 0: in = [xin(t) (3ch) | h0], out -> h0(other parity), c0 in-place
        convlstm_step<<<grid, 256>>>(
            xin + (long)t*CIN*PIX, CIN, (long)T*CIN*PIX,
            h0buf[p], (long)HID*PIX,
            CIN + HID, conv_w0, conv_b0,
            c0,
            h0buf[p^1], (long)HID*PIX,
            nullptr, 0, nullptr, nullptr);
        // layer 1: in = [h0_new (64ch) | h1], out -> h1(other parity) + out1[:,t]
        convlstm_step<<<grid, 256>>>(
            h0buf[p^1], HID, (long)HID*PIX,
            h1buf[p], (long)HID*PIX,
            2*HID, conv_w1, conv_b1,
            c1,
            h1buf[p^1], (long)HID*PIX,
            out1 + (long)t*HID*PIX, (long)T*HID*PIX,
            (t == T-1) ? h1fin : nullptr,
            (t == T-1) ? c1fin : nullptr);
    }
}

// round 7
// speedup vs baseline: 1.0638x; 1.0638x over previous
#include <cuda_runtime.h>
#include <cuda_bf16.h>
#include <math.h>
#include <stdint.h>

// Problem constants
#define B   8
#define T   16
#define CIN 3
#define HID 64
#define HW  64
#define PIX (HW*HW)          // 4096

#define KC    8              // input-channel chunk held in smem
#define INW_E 68             // in_e row width: col = g(col-1), cols 0..65 valid
#define INW_O 66             // in_o row width: col = g(col),   cols 0..65 valid

// ---------------- scratch (no allocation allowed) ----------------
__device__ float g_xin[B*T*CIN*PIX];          // attention-scaled input
__device__ float g_h0[2][B*HID*PIX];          // layer0 hidden, double buffered
__device__ float g_c0[B*HID*PIX];             // layer0 cell
__device__ float g_h1[2][B*HID*PIX];          // layer1 hidden, double buffered
__device__ float g_c1[B*HID*PIX];             // layer1 cell

// ---------------- packed f32x2 helpers ----------------
__device__ __forceinline__ void fma2(uint64_t& d, uint64_t a, uint64_t w) {
    asm("fma.rn.f32x2 %0, %1, %2, %0;" : "+l"(d) : "l"(a), "l"(w));
}
__device__ __forceinline__ void unpack2(uint64_t v, float& lo, float& hi) {
    uint32_t l, h;
    asm("mov.b64 {%0,%1}, %2;" : "=r"(l), "=r"(h) : "l"(v));
    lo = __uint_as_float(l); hi = __uint_as_float(h);
}

// ---------------- attention + input scaling ----------------
__global__ void attention_kernel(const float* __restrict__ x,
                                 const float* __restrict__ w1,
                                 const float* __restrict__ w2,
                                 float* __restrict__ xin)
{
    const int bt = blockIdx.x;                 // 0..127
    const float* xp = x  + (long)bt * CIN * PIX;
    float*       xo = xin + (long)bt * CIN * PIX;

    __shared__ float s_sum[256], s_max[256];
    __shared__ float chAvg[CIN], chMax[CIN], scale[CIN];

    for (int c = 0; c < CIN; ++c) {
        float s = 0.f, m = -INFINITY;
        for (int i = threadIdx.x; i < PIX; i += 256) {
            float v = xp[c*PIX + i];
            s += v; m = fmaxf(m, v);
        }
        s_sum[threadIdx.x] = s; s_max[threadIdx.x] = m;
        __syncthreads();
        for (int off = 128; off > 0; off >>= 1) {
            if (threadIdx.x < off) {
                s_sum[threadIdx.x] += s_sum[threadIdx.x + off];
                s_max[threadIdx.x] = fmaxf(s_max[threadIdx.x], s_max[threadIdx.x + off]);
            }
            __syncthreads();
        }
        if (threadIdx.x == 0) { chAvg[c] = s_sum[0] / (float)PIX; chMax[c] = s_max[0]; }
        __syncthreads();
    }
    if (threadIdx.x == 0) {
        float ha = w1[0]*chAvg[0] + w1[1]*chAvg[1] + w1[2]*chAvg[2];
        float hm = w1[0]*chMax[0] + w1[1]*chMax[1] + w1[2]*chMax[2];
        ha = fmaxf(ha, 0.f); hm = fmaxf(hm, 0.f);
        float hs = ha + hm;
        for (int c = 0; c < CIN; ++c)
            scale[c] = 1.f / (1.f + expf(-w2[c]*hs));
    }
    __syncthreads();
    for (int c = 0; c < CIN; ++c)
        for (int i = threadIdx.x; i < PIX; i += 256)
            xo[c*PIX + i] = xp[c*PIX + i] * scale[c];
}

// ---------------- fused conv(3x3 SAME) + LSTM pointwise step ----------------
// grid: (16 row-tiles, 8 hidden-groups, 8 batches), 256 threads.
// Warp owns one hidden channel; lane owns adjacent column pair (2*lane, 2*lane+1)
// for 4 rows -> 4 gates x 4 rows of f32x2 accumulators. All conv taps are
// aligned LDS.64 thanks to the dual shifted smem copies (in_e / in_o).
__global__ __launch_bounds__(256)
void convlstm_step(const float* __restrict__ srcA, int CA, long sA,
                   const float* __restrict__ srcB, long sB,
                   int Cin,
                   const float* __restrict__ W,        // [4*HID, Cin, 3,3]
                   const float* __restrict__ bias,     // [4*HID]
                   float* __restrict__ cState,         // [B,HID,PIX] in/out
                   float* __restrict__ hOut,  long hOutStride,
                   float* __restrict__ hOut2, long hOut2Stride,
                   float* __restrict__ hFin,  float* __restrict__ cFin)
{
    const int b    = blockIdx.z;
    const int warp = threadIdx.x >> 5;
    const int lane = threadIdx.x & 31;
    const int j    = blockIdx.y * 8 + warp;    // hidden channel
    const int r0   = blockIdx.x * 4;           // first output row

    __shared__ __align__(16) float in_e[KC*6*INW_E];   // [kc][6][68]: col = g(col-1)
    __shared__ __align__(16) float in_o[KC*6*INW_O];   // [kc][6][66]: col = g(col)
    __shared__ __align__(16) float w_s[8*KC*9*8];      // [wj][kc][kk][gate*2 dup]

    uint64_t acc[4][4];                                 // [gate][row] packed pairs
    #pragma unroll
    for (int g = 0; g < 4; ++g)
        #pragma unroll
        for (int r = 0; r < 4; ++r) acc[g][r] = 0ull;

    const float* srcAb = srcA + (long)b * sA;
    const float* srcBb = srcB + (long)b * sB;

    for (int c0 = 0; c0 < Cin; c0 += KC) {
        const int kcCnt = min(KC, Cin - c0);
        __syncthreads();
        // ---- stage input tile into both shifted copies ----
        const int total = kcCnt * 6 * INW_E;
        for (int idx = threadIdx.x; idx < total; idx += 256) {
            int col = idx % INW_E;               // 0..67
            int row = (idx / INW_E) % 6;
            int kc  = idx / (INW_E*6);
            int c   = c0 + kc;
            int gr  = r0 + row - 1;
            int gc  = col - 1;                   // global col for in_e
            float v = 0.f;
            if (gr >= 0 && gr < HW && gc >= 0 && gc < HW) {
                v = (c < CA) ? srcAb[(long)c      *PIX + gr*HW + gc]
                             : srcBb[(long)(c-CA) *PIX + gr*HW + gc];
            }
            in_e[(kc*6 + row)*INW_E + col] = v;
            if (gc >= 0 && gc < INW_O)
                in_o[(kc*6 + row)*INW_O + gc] = v;
        }
        // ---- stage weights, each duplicated into a {w,w} pair ----
        const int wtotal = 8 * kcCnt * 9 * 8;   // wj * kc * kk * (4 gates x 2 dup)
        for (int idx = threadIdx.x; idx < wtotal; idx += 256) {
            int g   = (idx >> 1) & 3;
            int kk  = (idx >> 3) % 9;
            int kc  = (idx / 72) % kcCnt;
            int wj  = idx / (72 * kcCnt);
            int oc  = g*HID + blockIdx.y*8 + wj;
            float v = W[((long)oc*Cin + c0 + kc)*9 + kk];
            w_s[((wj*KC + kc)*9 + kk)*8 + (idx & 7)] = v;
        }
        __syncthreads();

        // ---- accumulate ----
        for (int kc = 0; kc < kcCnt; ++kc) {
            const float* pE = in_e + kc*6*INW_E + 2*lane;
            const float* pO = in_o + kc*6*INW_O + 2*lane;
            const float* wp = w_s + (warp*KC + kc)*72;
            #pragma unroll
            for (int ky = 0; ky < 3; ++ky) {
                uint64_t A0[4], A1[4], A2[4];    // taps kx=0,1,2 (all aligned)
                #pragma unroll
                for (int r = 0; r < 4; ++r) {
                    A0[r] = *(const uint64_t*)(pE + (r + ky)*INW_E);
                    A1[r] = *(const uint64_t*)(pO + (r + ky)*INW_O);
                    A2[r] = *(const uint64_t*)(pE + (r + ky)*INW_E + 2);
                }
                #pragma unroll
                for (int kx = 0; kx < 3; ++kx) {
                    const int kk = ky*3 + kx;
                    ulonglong2 wAB = *(const ulonglong2*)(wp + kk*8);      // {w0,w0},{w1,w1}
                    ulonglong2 wCD = *(const ulonglong2*)(wp + kk*8 + 4);  // {w2,w2},{w3,w3}
                    #pragma unroll
                    for (int r = 0; r < 4; ++r) {
                        uint64_t a = (kx == 0) ? A0[r] : (kx == 1) ? A1[r] : A2[r];
                        fma2(acc[0][r], a, wAB.x);
                        fma2(acc[1][r], a, wAB.y);
                        fma2(acc[2][r], a, wCD.x);
                        fma2(acc[3][r], a, wCD.y);
                    }
                }
            }
        }
    }

    // ---- fused LSTM pointwise update (column pair per lane) ----
    const float bi = bias[j], bf = bias[HID + j], bo = bias[2*HID + j], bg = bias[3*HID + j];
    const long cBase = ((long)b*HID + j)*PIX;
    #pragma unroll
    for (int r = 0; r < 4; ++r) {
        const int  pix  = (r0 + r)*HW + 2*lane;
        const long cOff = cBase + pix;
        float i0,i1, f0,f1, o0,o1, g0,g1;
        unpack2(acc[0][r], i0, i1);
        unpack2(acc[1][r], f0, f1);
        unpack2(acc[2][r], o0, o1);
        unpack2(acc[3][r], g0, g1);

        float2 cOld = *(const float2*)(cState + cOff);

        float ig0 = 1.f/(1.f + __expf(-(i0 + bi)));
        float ig1 = 1.f/(1.f + __expf(-(i1 + bi)));
        float fg0 = 1.f/(1.f + __expf(-(f0 + bf)));
        float fg1 = 1.f/(1.f + __expf(-(f1 + bf)));
        float og0 = 1.f/(1.f + __expf(-(o0 + bo)));
        float og1 = 1.f/(1.f + __expf(-(o1 + bo)));
        float gg0 = tanhf(g0 + bg);
        float gg1 = tanhf(g1 + bg);

        float cN0 = fg0*cOld.x + ig0*gg0;
        float cN1 = fg1*cOld.y + ig1*gg1;
        float hN0 = og0*tanhf(cN0);
        float hN1 = og1*tanhf(cN1);

        *(float2*)(cState + cOff) = make_float2(cN0, cN1);
        *(float2*)(hOut + (long)b*hOutStride + (long)j*PIX + pix) = make_float2(hN0, hN1);
        if (hOut2) *(float2*)(hOut2 + (long)b*hOut2Stride + (long)j*PIX + pix) = make_float2(hN0, hN1);
        if (hFin)  *(float2*)(hFin + cBase + pix) = make_float2(hN0, hN1);
        if (cFin)  *(float2*)(cFin + cBase + pix) = make_float2(cN0, cN1);
    }
}

// ---------------- host ----------------
extern "C" void kernel_launch(void* const* d_in, const int* in_sizes, int n_in,
                              void* d_out, int out_size)
{
    const float* x       = (const float*)d_in[0];
    const float* att_w1  = (const float*)d_in[1];
    const float* att_w2  = (const float*)d_in[2];
    const float* conv_w0 = (const float*)d_in[3];
    const float* conv_b0 = (const float*)d_in[4];
    const float* conv_w1 = (const float*)d_in[5];
    const float* conv_b1 = (const float*)d_in[6];
    float* out = (float*)d_out;

    float *xin, *h0_0, *h0_1, *c0, *h1_0, *h1_1, *c1;
    cudaGetSymbolAddress((void**)&xin,  g_xin);
    cudaGetSymbolAddress((void**)&h0_0, g_h0);   h0_1 = h0_0 + (long)B*HID*PIX;
    cudaGetSymbolAddress((void**)&c0,   g_c0);
    cudaGetSymbolAddress((void**)&h1_0, g_h1);   h1_1 = h1_0 + (long)B*HID*PIX;
    cudaGetSymbolAddress((void**)&c1,   g_c1);

    const size_t stBytes = (size_t)B*HID*PIX*sizeof(float);
    cudaMemsetAsync(h0_0, 0, stBytes);
    cudaMemsetAsync(c0,   0, stBytes);
    cudaMemsetAsync(h1_0, 0, stBytes);
    cudaMemsetAsync(c1,   0, stBytes);

    attention_kernel<<<B*T, 256>>>(x, att_w1, att_w2, xin);

    float* h0buf[2] = {h0_0, h0_1};
    float* h1buf[2] = {h1_0, h1_1};

    float* out1  = out;                                  // [B,T,HID,PIX]
    float* h1fin = out + (long)B*T*HID*PIX;              // [B,HID,PIX]
    float* c1fin = h1fin + (long)B*HID*PIX;              // [B,HID,PIX]

    dim3 grid(HW/4, HID/8, B);

    for (int t = 0; t < T; ++t) {
        const int p = t & 1;
        // layer 0: in = [xin(t) (3ch) | h0], out -> h0(other parity), c0 in-place
        convlstm_step<<<grid, 256>>>(
            xin + (long)t*CIN*PIX, CIN, (long)T*CIN*PIX,
            h0buf[p], (long)HID*PIX,
            CIN + HID, conv_w0, conv_b0,
            c0,
            h0buf[p^1], (long)HID*PIX,
            nullptr, 0, nullptr, nullptr);
        // layer 1: in = [h0_new (64ch) | h1], out -> h1(other parity) + out1[:,t]
        convlstm_step<<<grid, 256>>>(
            h0buf[p^1], HID, (long)HID*PIX,
            h1buf[p], (long)HID*PIX,
            2*HID, conv_w1, conv_b1,
            c1,
            h1buf[p^1], (long)HID*PIX,
            out1 + (long)t*HID*PIX, (long)T*HID*PIX,
            (t == T-1) ? h1fin : nullptr,
            (t == T-1) ? c1fin : nullptr);
    }
}

// round 12
// speedup vs baseline: 1.8565x; 1.7452x over previous
#include <cuda_runtime.h>
#include <cuda_bf16.h>
#include <math.h>
#include <stdint.h>

// Problem constants
#define B   8
#define T   16
#define CIN 3
#define HID 64
#define HW  64
#define PIX (HW*HW)          // 4096

#define KC    8              // input-channel chunk held in smem
#define WE    68             // in_e row width: in_e[c] = g(c-1), valid c 0..65
#define WO    64             // in_o row width: in_o[c] = g(c)

// ---------------- scratch (no allocation allowed) ----------------
__device__ float g_xin[B*T*CIN*PIX];          // attention-scaled input
__device__ float g_h0[2][B*HID*PIX];          // layer0 hidden, double buffered
__device__ float g_c0[B*HID*PIX];             // layer0 cell
__device__ float g_h1[2][B*HID*PIX];          // layer1 hidden, double buffered
__device__ float g_c1[B*HID*PIX];             // layer1 cell

// ---------------- packed f32x2 helpers ----------------
__device__ __forceinline__ void fma2(uint64_t& d, uint64_t a, uint64_t w) {
    asm("fma.rn.f32x2 %0, %1, %2, %0;" : "+l"(d) : "l"(a), "l"(w));
}
__device__ __forceinline__ void unpack2(uint64_t v, float& lo, float& hi) {
    uint32_t l, h;
    asm("mov.b64 {%0,%1}, %2;" : "=r"(l), "=r"(h) : "l"(v));
    lo = __uint_as_float(l); hi = __uint_as_float(h);
}

// ---------------- attention + input scaling ----------------
__global__ void attention_kernel(const float* __restrict__ x,
                                 const float* __restrict__ w1,
                                 const float* __restrict__ w2,
                                 float* __restrict__ xin)
{
    const int bt = blockIdx.x;                 // 0..127
    const float* xp = x  + (long)bt * CIN * PIX;
    float*       xo = xin + (long)bt * CIN * PIX;

    __shared__ float s_sum[256], s_max[256];
    __shared__ float chAvg[CIN], chMax[CIN], scale[CIN];

    for (int c = 0; c < CIN; ++c) {
        float s = 0.f, m = -INFINITY;
        for (int i = threadIdx.x; i < PIX; i += 256) {
            float v = xp[c*PIX + i];
            s += v; m = fmaxf(m, v);
        }
        s_sum[threadIdx.x] = s; s_max[threadIdx.x] = m;
        __syncthreads();
        for (int off = 128; off > 0; off >>= 1) {
            if (threadIdx.x < off) {
                s_sum[threadIdx.x] += s_sum[threadIdx.x + off];
                s_max[threadIdx.x] = fmaxf(s_max[threadIdx.x], s_max[threadIdx.x + off]);
            }
            __syncthreads();
        }
        if (threadIdx.x == 0) { chAvg[c] = s_sum[0] / (float)PIX; chMax[c] = s_max[0]; }
        __syncthreads();
    }
    if (threadIdx.x == 0) {
        float ha = w1[0]*chAvg[0] + w1[1]*chAvg[1] + w1[2]*chAvg[2];
        float hm = w1[0]*chMax[0] + w1[1]*chMax[1] + w1[2]*chMax[2];
        ha = fmaxf(ha, 0.f); hm = fmaxf(hm, 0.f);
        float hs = ha + hm;
        for (int c = 0; c < CIN; ++c)
            scale[c] = 1.f / (1.f + expf(-w2[c]*hs));
    }
    __syncthreads();
    for (int c = 0; c < CIN; ++c)
        for (int i = threadIdx.x; i < PIX; i += 256)
            xo[c*PIX + i] = xp[c*PIX + i] * scale[c];
}

// ---------------- fused conv(3x3 SAME) + LSTM, dual-layer wavefront ----------------
// grid: (16 row-tiles, 8 hidden-groups, 8 or 16 z). mode 0: layer0 only,
// mode 1: layer1 only, mode 2: z<8 -> layer0, z>=8 -> layer1.
// Warp owns one hidden channel; lane owns column pair (2l, 2l+1) for 4 rows.
__global__ __launch_bounds__(256)
void convlstm_dual(int mode,
    // layer0 params
    const float* __restrict__ a0A, long a0sA,        // xin(t), CA=3
    const float* __restrict__ a0B,                   // h0 prev
    const float* __restrict__ W0, const float* __restrict__ bias0,
    float* __restrict__ c0St, float* __restrict__ h0Out,
    // layer1 params
    const float* __restrict__ a1A,                   // h0 new, CA=64
    const float* __restrict__ a1B,                   // h1 prev
    const float* __restrict__ W1, const float* __restrict__ bias1,
    float* __restrict__ c1St, float* __restrict__ h1Out,
    float* __restrict__ out1Slice,                   // out1[:,t1]
    float* __restrict__ hFin, float* __restrict__ cFin)
{
    int z = blockIdx.z;
    int layer, b;
    if (mode == 2) { layer = z >> 3; b = z & 7; }
    else           { layer = mode;   b = z; }

    // select per-layer params
    const float* srcA; long sA; int CA; const float* srcB; int Cin;
    const float* W; const float* bias;
    float* cState; float* hOut; float* hOut2; float* hF; float* cF;
    if (layer == 0) {
        srcA = a0A; sA = a0sA; CA = CIN; srcB = a0B; Cin = CIN + HID;
        W = W0; bias = bias0; cState = c0St; hOut = h0Out;
        hOut2 = nullptr; hF = nullptr; cF = nullptr;
    } else {
        srcA = a1A; sA = (long)HID*PIX; CA = HID; srcB = a1B; Cin = 2*HID;
        W = W1; bias = bias1; cState = c1St; hOut = h1Out;
        hOut2 = out1Slice; hF = hFin; cF = cFin;
    }

    const int warp = threadIdx.x >> 5;
    const int lane = threadIdx.x & 31;
    const int j    = blockIdx.y * 8 + warp;    // hidden channel
    const int r0   = blockIdx.x * 4;           // first output row

    __shared__ __align__(16) float in_e[KC*6*WE];      // [kc][6][68]
    __shared__ __align__(16) float in_o[KC*6*WO];      // [kc][6][64]
    __shared__ __align__(16) float w_s[8*KC*9*8];      // [wj][kc][kk][8 dup]

    uint64_t acc[4][4];                                 // [gate][row]
    #pragma unroll
    for (int g = 0; g < 4; ++g)
        #pragma unroll
        for (int r = 0; r < 4; ++r) acc[g][r] = 0ull;

    const float* srcAb = srcA + (long)b * sA;
    const float* srcBb = srcB + (long)b * (long)HID*PIX;

    const int jw = blockIdx.y * 8;   // base channel for weight staging

    for (int c0 = 0; c0 < Cin; c0 += KC) {
        const int kcCnt = min(KC, Cin - c0);
        __syncthreads();

        // ---- stage input: warp w handles kc = w (div-free) ----
        if (warp < kcCnt) {
            const int c = c0 + warp;
            const float* srcRow = (c < CA) ? (srcAb + (long)c*PIX)
                                           : (srcBb + (long)(c - CA)*PIX);
            #pragma unroll
            for (int row = 0; row < 6; ++row) {
                const int gr = r0 + row - 1;
                float2 v = make_float2(0.f, 0.f);
                if (gr >= 0 && gr < HW)
                    v = *(const float2*)(srcRow + gr*HW + 2*lane);
                const int eb = (warp*6 + row)*WE;
                const int ob = (warp*6 + row)*WO;
                *(float2*)(in_o + ob + 2*lane) = v;      // in_o[c] = g(c)
                in_e[eb + 2*lane + 1] = v.x;             // in_e[c] = g(c-1)
                in_e[eb + 2*lane + 2] = v.y;
                if (lane == 0) { in_e[eb] = 0.f; in_e[eb + 65] = 0.f; }
            }
        }

        // ---- stage weights (shift/mask only): warp = wj, each dup'd {w,w} ----
        {
            const int oc_base = jw + warp;   // channel of this warp
            for (int kc = 0; kc < kcCnt; ++kc) {
                const long wRow = ((long)(c0 + kc))*9;
                float* dst = w_s + ((warp*KC + kc)*9)*8;
                #pragma unroll
                for (int v = lane; v < 72; v += 32) {
                    int kk = v >> 3;
                    int g  = (v >> 1) & 3;
                    dst[v] = W[((long)(g*HID + oc_base)*Cin)*9 + wRow + kk];
                }
            }
        }
        __syncthreads();

        // ---- accumulate: iterate 6 input rows, apply to all valid (ky,r) ----
        for (int kc = 0; kc < kcCnt; ++kc) {
            const float* pE = in_e + kc*6*WE + 2*lane;
            const float* pO = in_o + kc*6*WO + 2*lane;
            const float* wp = w_s + (warp*KC + kc)*72;
            #pragma unroll
            for (int ir = 0; ir < 6; ++ir) {
                uint64_t aE  = *(const uint64_t*)(pE + ir*WE);       // kx=0
                uint64_t aO  = *(const uint64_t*)(pO + ir*WO);       // kx=1
                uint64_t aE2 = *(const uint64_t*)(pE + ir*WE + 2);   // kx=2
                #pragma unroll
                for (int ky = 0; ky < 3; ++ky) {
                    const int r = ir - ky;
                    if (r >= 0 && r < 4) {
                        #pragma unroll
                        for (int kx = 0; kx < 3; ++kx) {
                            const int kk = ky*3 + kx;
                            ulonglong2 wAB = *(const ulonglong2*)(wp + kk*8);
                            ulonglong2 wCD = *(const ulonglong2*)(wp + kk*8 + 4);
                            uint64_t a = (kx == 0) ? aE : (kx == 1) ? aO : aE2;
                            fma2(acc[0][r], a, wAB.x);
                            fma2(acc[1][r], a, wAB.y);
                            fma2(acc[2][r], a, wCD.x);
                            fma2(acc[3][r], a, wCD.y);
                        }
                    }
                }
            }
        }
    }

    // ---- fused LSTM pointwise update (column pair per lane) ----
    const float bi = bias[j], bf = bias[HID + j], bo = bias[2*HID + j], bg = bias[3*HID + j];
    const long cBase = ((long)b*HID + j)*PIX;
    #pragma unroll
    for (int r = 0; r < 4; ++r) {
        const int  pix  = (r0 + r)*HW + 2*lane;
        const long cOff = cBase + pix;
        float i0,i1, f0,f1, o0,o1, g0,g1;
        unpack2(acc[0][r], i0, i1);
        unpack2(acc[1][r], f0, f1);
        unpack2(acc[2][r], o0, o1);
        unpack2(acc[3][r], g0, g1);

        float2 cOld = *(const float2*)(cState + cOff);

        float ig0 = 1.f/(1.f + __expf(-(i0 + bi)));
        float ig1 = 1.f/(1.f + __expf(-(i1 + bi)));
        float fg0 = 1.f/(1.f + __expf(-(f0 + bf)));
        float fg1 = 1.f/(1.f + __expf(-(f1 + bf)));
        float og0 = 1.f/(1.f + __expf(-(o0 + bo)));
        float og1 = 1.f/(1.f + __expf(-(o1 + bo)));
        float gg0 = tanhf(g0 + bg);
        float gg1 = tanhf(g1 + bg);

        float cN0 = fg0*cOld.x + ig0*gg0;
        float cN1 = fg1*cOld.y + ig1*gg1;
        float hN0 = og0*tanhf(cN0);
        float hN1 = og1*tanhf(cN1);

        *(float2*)(cState + cOff) = make_float2(cN0, cN1);
        *(float2*)(hOut + cBase + pix) = make_float2(hN0, hN1);
        if (hOut2) *(float2*)(hOut2 + (long)b*(long)T*HID*PIX + (long)j*PIX + pix) = make_float2(hN0, hN1);
        if (hF)    *(float2*)(hF + cBase + pix) = make_float2(hN0, hN1);
        if (cF)    *(float2*)(cF + cBase + pix) = make_float2(cN0, cN1);
    }
}

// ---------------- host ----------------
extern "C" void kernel_launch(void* const* d_in, const int* in_sizes, int n_in,
                              void* d_out, int out_size)
{
    const float* x       = (const float*)d_in[0];
    const float* att_w1  = (const float*)d_in[1];
    const float* att_w2  = (const float*)d_in[2];
    const float* conv_w0 = (const float*)d_in[3];
    const float* conv_b0 = (const float*)d_in[4];
    const float* conv_w1 = (const float*)d_in[5];
    const float* conv_b1 = (const float*)d_in[6];
    float* out = (float*)d_out;

    float *xin, *h0_0, *h0_1, *c0, *h1_0, *h1_1, *c1;
    cudaGetSymbolAddress((void**)&xin,  g_xin);
    cudaGetSymbolAddress((void**)&h0_0, g_h0);   h0_1 = h0_0 + (long)B*HID*PIX;
    cudaGetSymbolAddress((void**)&c0,   g_c0);
    cudaGetSymbolAddress((void**)&h1_0, g_h1);   h1_1 = h1_0 + (long)B*HID*PIX;
    cudaGetSymbolAddress((void**)&c1,   g_c1);

    const size_t stBytes = (size_t)B*HID*PIX*sizeof(float);
    cudaMemsetAsync(h0_0, 0, stBytes);
    cudaMemsetAsync(c0,   0, stBytes);
    cudaMemsetAsync(h1_0, 0, stBytes);
    cudaMemsetAsync(c1,   0, stBytes);

    attention_kernel<<<B*T, 256>>>(x, att_w1, att_w2, xin);

    float* h0buf[2] = {h0_0, h0_1};
    float* h1buf[2] = {h1_0, h1_1};

    float* out1  = out;                                  // [B,T,HID,PIX]
    float* h1fin = out + (long)B*T*HID*PIX;              // [B,HID,PIX]
    float* c1fin = h1fin + (long)B*HID*PIX;              // [B,HID,PIX]

    // wavefront: step s runs layer0(t=s) and layer1(t=s-1) concurrently
    for (int s = 0; s <= T; ++s) {
        const int t0 = s;            // layer0 timestep
        const int t1 = s - 1;        // layer1 timestep
        const int mode = (s == 0) ? 0 : (s == T) ? 1 : 2;
        const int zdim = (mode == 2) ? 16 : 8;
        dim3 grid(HW/4, HID/8, zdim);

        const int p0 = t0 & 1;                 // layer0 parity (valid when t0<T)
        const int p1 = (t1 >= 0) ? (t1 & 1) : 0;

        convlstm_dual<<<grid, 256>>>(mode,
            // layer0: in = [xin(t0) | h0buf[p0]] -> h0buf[p0^1], c0
            (t0 < T) ? xin + (long)t0*CIN*PIX : xin, (long)T*CIN*PIX,
            h0buf[p0],
            conv_w0, conv_b0,
            c0, h0buf[p0^1],
            // layer1: in = [h0buf[p1^1] | h1buf[p1]] -> h1buf[p1^1], c1, out1[:,t1]
            h0buf[p1^1],
            h1buf[p1],
            conv_w1, conv_b1,
            c1, h1buf[p1^1],
            (t1 >= 0) ? out1 + (long)t1*HID*PIX : out1,
            (t1 == T-1) ? h1fin : nullptr,
            (t1 == T-1) ? c1fin : nullptr);
    }
}

// round 13
// speedup vs baseline: 1.8580x; 1.0008x over previous
#include <cuda_runtime.h>
#include <cuda_bf16.h>
#include <math.h>
#include <stdint.h>

// Problem constants
#define B   8
#define T   16
#define CIN 3
#define HID 64
#define HW  64
#define PIX (HW*HW)          // 4096

#define KC    8              // input-channel chunk held in smem
#define WE    68             // in_e row width: in_e[c] = g(c-1), valid c 0..65
#define WO    64             // in_o row width: in_o[c] = g(c)

// ---------------- scratch (no allocation allowed) ----------------
__device__ float g_xin[B*T*CIN*PIX];          // attention-scaled input
__device__ float g_h0[2][B*HID*PIX];          // layer0 hidden, double buffered
__device__ float g_c0[B*HID*PIX];             // layer0 cell
__device__ float g_h1[2][B*HID*PIX];          // layer1 hidden, double buffered
__device__ float g_c1[B*HID*PIX];             // layer1 cell

// ---------------- packed f32x2 helpers ----------------
__device__ __forceinline__ void fma2(uint64_t& d, uint64_t a, uint64_t w) {
    asm("fma.rn.f32x2 %0, %1, %2, %0;" : "+l"(d) : "l"(a), "l"(w));
}
__device__ __forceinline__ void unpack2(uint64_t v, float& lo, float& hi) {
    uint32_t l, h;
    asm("mov.b64 {%0,%1}, %2;" : "=r"(l), "=r"(h) : "l"(v));
    lo = __uint_as_float(l); hi = __uint_as_float(h);
}

// ---------------- attention + input scaling ----------------
__global__ void attention_kernel(const float* __restrict__ x,
                                 const float* __restrict__ w1,
                                 const float* __restrict__ w2,
                                 float* __restrict__ xin)
{
    const int bt = blockIdx.x;                 // 0..127
    const float* xp = x  + (long)bt * CIN * PIX;
    float*       xo = xin + (long)bt * CIN * PIX;

    __shared__ float s_sum[256], s_max[256];
    __shared__ float chAvg[CIN], chMax[CIN], scale[CIN];

    for (int c = 0; c < CIN; ++c) {
        float s = 0.f, m = -INFINITY;
        for (int i = threadIdx.x; i < PIX; i += 256) {
            float v = xp[c*PIX + i];
            s += v; m = fmaxf(m, v);
        }
        s_sum[threadIdx.x] = s; s_max[threadIdx.x] = m;
        __syncthreads();
        for (int off = 128; off > 0; off >>= 1) {
            if (threadIdx.x < off) {
                s_sum[threadIdx.x] += s_sum[threadIdx.x + off];
                s_max[threadIdx.x] = fmaxf(s_max[threadIdx.x], s_max[threadIdx.x + off]);
            }
            __syncthreads();
        }
        if (threadIdx.x == 0) { chAvg[c] = s_sum[0] / (float)PIX; chMax[c] = s_max[0]; }
        __syncthreads();
    }
    if (threadIdx.x == 0) {
        float ha = w1[0]*chAvg[0] + w1[1]*chAvg[1] + w1[2]*chAvg[2];
        float hm = w1[0]*chMax[0] + w1[1]*chMax[1] + w1[2]*chMax[2];
        ha = fmaxf(ha, 0.f); hm = fmaxf(hm, 0.f);
        float hs = ha + hm;
        for (int c = 0; c < CIN; ++c)
            scale[c] = 1.f / (1.f + expf(-w2[c]*hs));
    }
    __syncthreads();
    for (int c = 0; c < CIN; ++c)
        for (int i = threadIdx.x; i < PIX; i += 256)
            xo[c*PIX + i] = xp[c*PIX + i] * scale[c];
}

// ---------------- fused conv(3x3 SAME) + LSTM, dual-layer wavefront ----------------
// grid: (16 row-tiles, 8 hidden-groups, 8 or 16 z). mode 0: layer0 only,
// mode 1: layer1 only, mode 2: z<8 -> layer0, z>=8 -> layer1.
// Warp owns one hidden channel; lane owns column pair (2l, 2l+1) for 4 rows.
__global__ __launch_bounds__(256)
void convlstm_dual(int mode,
    // layer0 params
    const float* __restrict__ a0A, long a0sA,        // xin(t), CA=3
    const float* __restrict__ a0B,                   // h0 prev
    const float* __restrict__ W0, const float* __restrict__ bias0,
    float* __restrict__ c0St, float* __restrict__ h0Out,
    // layer1 params
    const float* __restrict__ a1A,                   // h0 new, CA=64
    const float* __restrict__ a1B,                   // h1 prev
    const float* __restrict__ W1, const float* __restrict__ bias1,
    float* __restrict__ c1St, float* __restrict__ h1Out,
    float* __restrict__ out1Slice,                   // out1[:,t1]
    float* __restrict__ hFin, float* __restrict__ cFin)
{
    int z = blockIdx.z;
    int layer, b;
    if (mode == 2) { layer = z >> 3; b = z & 7; }
    else           { layer = mode;   b = z; }

    // select per-layer params
    const float* srcA; long sA; int CA; const float* srcB; int Cin;
    const float* W; const float* bias;
    float* cState; float* hOut; float* hOut2; float* hF; float* cF;
    if (layer == 0) {
        srcA = a0A; sA = a0sA; CA = CIN; srcB = a0B; Cin = CIN + HID;
        W = W0; bias = bias0; cState = c0St; hOut = h0Out;
        hOut2 = nullptr; hF = nullptr; cF = nullptr;
    } else {
        srcA = a1A; sA = (long)HID*PIX; CA = HID; srcB = a1B; Cin = 2*HID;
        W = W1; bias = bias1; cState = c1St; hOut = h1Out;
        hOut2 = out1Slice; hF = hFin; cF = cFin;
    }

    const int warp = threadIdx.x >> 5;
    const int lane = threadIdx.x & 31;
    const int j    = blockIdx.y * 8 + warp;    // hidden channel
    const int r0   = blockIdx.x * 4;           // first output row

    __shared__ __align__(16) float in_e[KC*6*WE];      // [kc][6][68]
    __shared__ __align__(16) float in_o[KC*6*WO];      // [kc][6][64]
    __shared__ __align__(16) float w_s[8*KC*9*8];      // [wj][kc][kk][8 dup]

    uint64_t acc[4][4];                                 // [gate][row]
    #pragma unroll
    for (int g = 0; g < 4; ++g)
        #pragma unroll
        for (int r = 0; r < 4; ++r) acc[g][r] = 0ull;

    const float* srcAb = srcA + (long)b * sA;
    const float* srcBb = srcB + (long)b * (long)HID*PIX;

    const int jw = blockIdx.y * 8;   // base channel for weight staging

    for (int c0 = 0; c0 < Cin; c0 += KC) {
        const int kcCnt = min(KC, Cin - c0);
        __syncthreads();

        // ---- stage input: warp w handles kc = w (div-free) ----
        if (warp < kcCnt) {
            const int c = c0 + warp;
            const float* srcRow = (c < CA) ? (srcAb + (long)c*PIX)
                                           : (srcBb + (long)(c - CA)*PIX);
            #pragma unroll
            for (int row = 0; row < 6; ++row) {
                const int gr = r0 + row - 1;
                float2 v = make_float2(0.f, 0.f);
                if (gr >= 0 && gr < HW)
                    v = *(const float2*)(srcRow + gr*HW + 2*lane);
                const int eb = (warp*6 + row)*WE;
                const int ob = (warp*6 + row)*WO;
                *(float2*)(in_o + ob + 2*lane) = v;      // in_o[c] = g(c)
                in_e[eb + 2*lane + 1] = v.x;             // in_e[c] = g(c-1)
                in_e[eb + 2*lane + 2] = v.y;
                if (lane == 0) { in_e[eb] = 0.f; in_e[eb + 65] = 0.f; }
            }
        }

        // ---- stage weights (shift/mask only): warp = wj, each dup'd {w,w} ----
        {
            const int oc_base = jw + warp;   // channel of this warp
            for (int kc = 0; kc < kcCnt; ++kc) {
                const long wRow = ((long)(c0 + kc))*9;
                float* dst = w_s + ((warp*KC + kc)*9)*8;
                #pragma unroll
                for (int v = lane; v < 72; v += 32) {
                    int kk = v >> 3;
                    int g  = (v >> 1) & 3;
                    dst[v] = W[((long)(g*HID + oc_base)*Cin)*9 + wRow + kk];
                }
            }
        }
        __syncthreads();

        // ---- accumulate: iterate 6 input rows, apply to all valid (ky,r) ----
        for (int kc = 0; kc < kcCnt; ++kc) {
            const float* pE = in_e + kc*6*WE + 2*lane;
            const float* pO = in_o + kc*6*WO + 2*lane;
            const float* wp = w_s + (warp*KC + kc)*72;
            #pragma unroll
            for (int ir = 0; ir < 6; ++ir) {
                uint64_t aE  = *(const uint64_t*)(pE + ir*WE);       // kx=0
                uint64_t aO  = *(const uint64_t*)(pO + ir*WO);       // kx=1
                uint64_t aE2 = *(const uint64_t*)(pE + ir*WE + 2);   // kx=2
                #pragma unroll
                for (int ky = 0; ky < 3; ++ky) {
                    const int r = ir - ky;
                    if (r >= 0 && r < 4) {
                        #pragma unroll
                        for (int kx = 0; kx < 3; ++kx) {
                            const int kk = ky*3 + kx;
                            ulonglong2 wAB = *(const ulonglong2*)(wp + kk*8);
                            ulonglong2 wCD = *(const ulonglong2*)(wp + kk*8 + 4);
                            uint64_t a = (kx == 0) ? aE : (kx == 1) ? aO : aE2;
                            fma2(acc[0][r], a, wAB.x);
                            fma2(acc[1][r], a, wAB.y);
                            fma2(acc[2][r], a, wCD.x);
                            fma2(acc[3][r], a, wCD.y);
                        }
                    }
                }
            }
        }
    }

    // ---- fused LSTM pointwise update (column pair per lane) ----
    const float bi = bias[j], bf = bias[HID + j], bo = bias[2*HID + j], bg = bias[3*HID + j];
    const long cBase = ((long)b*HID + j)*PIX;
    #pragma unroll
    for (int r = 0; r < 4; ++r) {
        const int  pix  = (r0 + r)*HW + 2*lane;
        const long cOff = cBase + pix;
        float i0,i1, f0,f1, o0,o1, g0,g1;
        unpack2(acc[0][r], i0, i1);
        unpack2(acc[1][r], f0, f1);
        unpack2(acc[2][r], o0, o1);
        unpack2(acc[3][r], g0, g1);

        float2 cOld = *(const float2*)(cState + cOff);

        float ig0 = 1.f/(1.f + __expf(-(i0 + bi)));
        float ig1 = 1.f/(1.f + __expf(-(i1 + bi)));
        float fg0 = 1.f/(1.f + __expf(-(f0 + bf)));
        float fg1 = 1.f/(1.f + __expf(-(f1 + bf)));
        float og0 = 1.f/(1.f + __expf(-(o0 + bo)));
        float og1 = 1.f/(1.f + __expf(-(o1 + bo)));
        float gg0 = tanhf(g0 + bg);
        float gg1 = tanhf(g1 + bg);

        float cN0 = fg0*cOld.x + ig0*gg0;
        float cN1 = fg1*cOld.y + ig1*gg1;
        float hN0 = og0*tanhf(cN0);
        float hN1 = og1*tanhf(cN1);

        *(float2*)(cState + cOff) = make_float2(cN0, cN1);
        *(float2*)(hOut + cBase + pix) = make_float2(hN0, hN1);
        if (hOut2) *(float2*)(hOut2 + (long)b*(long)T*HID*PIX + (long)j*PIX + pix) = make_float2(hN0, hN1);
        if (hF)    *(float2*)(hF + cBase + pix) = make_float2(hN0, hN1);
        if (cF)    *(float2*)(cF + cBase + pix) = make_float2(cN0, cN1);
    }
}

// ---------------- host ----------------
extern "C" void kernel_launch(void* const* d_in, const int* in_sizes, int n_in,
                              void* d_out, int out_size)
{
    const float* x       = (const float*)d_in[0];
    const float* att_w1  = (const float*)d_in[1];
    const float* att_w2  = (const float*)d_in[2];
    const float* conv_w0 = (const float*)d_in[3];
    const float* conv_b0 = (const float*)d_in[4];
    const float* conv_w1 = (const float*)d_in[5];
    const float* conv_b1 = (const float*)d_in[6];
    float* out = (float*)d_out;

    float *xin, *h0_0, *h0_1, *c0, *h1_0, *h1_1, *c1;
    cudaGetSymbolAddress((void**)&xin,  g_xin);
    cudaGetSymbolAddress((void**)&h0_0, g_h0);   h0_1 = h0_0 + (long)B*HID*PIX;
    cudaGetSymbolAddress((void**)&c0,   g_c0);
    cudaGetSymbolAddress((void**)&h1_0, g_h1);   h1_1 = h1_0 + (long)B*HID*PIX;
    cudaGetSymbolAddress((void**)&c1,   g_c1);

    const size_t stBytes = (size_t)B*HID*PIX*sizeof(float);
    cudaMemsetAsync(h0_0, 0, stBytes);
    cudaMemsetAsync(c0,   0, stBytes);
    cudaMemsetAsync(h1_0, 0, stBytes);
    cudaMemsetAsync(c1,   0, stBytes);

    attention_kernel<<<B*T, 256>>>(x, att_w1, att_w2, xin);

    float* h0buf[2] = {h0_0, h0_1};
    float* h1buf[2] = {h1_0, h1_1};

    float* out1  = out;                                  // [B,T,HID,PIX]
    float* h1fin = out + (long)B*T*HID*PIX;              // [B,HID,PIX]
    float* c1fin = h1fin + (long)B*HID*PIX;              // [B,HID,PIX]

    // wavefront: step s runs layer0(t=s) and layer1(t=s-1) concurrently
    for (int s = 0; s <= T; ++s) {
        const int t0 = s;            // layer0 timestep
        const int t1 = s - 1;        // layer1 timestep
        const int mode = (s == 0) ? 0 : (s == T) ? 1 : 2;
        const int zdim = (mode == 2) ? 16 : 8;
        dim3 grid(HW/4, HID/8, zdim);

        const int p0 = t0 & 1;                 // layer0 parity (valid when t0<T)
        const int p1 = (t1 >= 0) ? (t1 & 1) : 0;

        convlstm_dual<<<grid, 256>>>(mode,
            // layer0: in = [xin(t0) | h0buf[p0]] -> h0buf[p0^1], c0
            (t0 < T) ? xin + (long)t0*CIN*PIX : xin, (long)T*CIN*PIX,
            h0buf[p0],
            conv_w0, conv_b0,
            c0, h0buf[p0^1],
            // layer1: in = [h0buf[p1^1] | h1buf[p1]] -> h1buf[p1^1], c1, out1[:,t1]
            h0buf[p1^1],
            h1buf[p1],
            conv_w1, conv_b1,
            c1, h1buf[p1^1],
            (t1 >= 0) ? out1 + (long)t1*HID*PIX : out1,
            (t1 == T-1) ? h1fin : nullptr,
            (t1 == T-1) ? c1fin : nullptr);
    }
}